// round 12
// baseline (speedup 1.0000x reference)
#include <cuda_runtime.h>
#include <cstdint>

#define NNODES 64
#define NEDGES 128
#define NGRAPH 4

typedef unsigned long long ull;

#define O1 2000
#define O2 500
#define O3 100
#define K2 2000
#define K3 500
#define G2 8
#define G3 6

// ---------------- scratch ----------------
__device__ float g_A2T[6 * K2 * 64];        // 12000 x 64
__device__ float g_A3T[6 * K3 * 64];        // 3000 x 64
__device__ float g_Z1 [64 * O1];
__device__ float g_Z2p[G2 * 64 * O2];       // grouped split-K partials
__device__ float g_Z3p[G3 * 64 * O3];

// ---------------- helpers ----------------
__device__ __forceinline__ void gdc_wait() {
    asm volatile("griddepcontrol.wait;" ::: "memory");
}
__device__ __forceinline__ void gdc_launch() {
    asm volatile("griddepcontrol.launch_dependents;" ::: "memory");
}
__device__ __forceinline__ ull dup2(float x) {
    ull r; asm("mov.b64 %0, {%1, %1};" : "=l"(r) : "f"(x)); return r;
}
__device__ __forceinline__ void fma2(ull &d, ull a, ull b) {
    asm("fma.rn.f32x2 %0, %1, %2, %3;" : "=l"(d) : "l"(a), "l"(b), "l"(d));
}
__device__ __forceinline__ float2 unpk(ull v) {
    float2 r; asm("mov.b64 {%0, %1}, %2;" : "=f"(r.x), "=f"(r.y) : "l"(v)); return r;
}
__device__ __forceinline__ void cpa16(void* dst, const void* src) {
    uint32_t d = (uint32_t)__cvta_generic_to_shared(dst);
    asm volatile("cp.async.cg.shared.global [%0], [%1], 16;\n" :: "r"(d), "l"(src));
}
__device__ __forceinline__ void cpa_commit() {
    asm volatile("cp.async.commit_group;\n" ::: "memory");
}
template<int N> __device__ __forceinline__ void cpa_wait() {
    asm volatile("cp.async.wait_group %0;\n" :: "n"(N) : "memory");
}

#define FMA_BLOCK \
    ull b0 = dup2(bL.x), b1 = dup2(bL.y), b2 = dup2(bL.z), b3 = dup2(bL.w); \
    ull b4 = dup2(bH.x), b5 = dup2(bH.y), b6 = dup2(bH.z), b7 = dup2(bH.w); \
    fma2(acc[0][0], a0, b0); fma2(acc[0][1], a0, b1); fma2(acc[0][2], a0, b2); fma2(acc[0][3], a0, b3); \
    fma2(acc[0][4], a0, b4); fma2(acc[0][5], a0, b5); fma2(acc[0][6], a0, b6); fma2(acc[0][7], a0, b7); \
    fma2(acc[1][0], a1, b0); fma2(acc[1][1], a1, b1); fma2(acc[1][2], a1, b2); fma2(acc[1][3], a1, b3); \
    fma2(acc[1][4], a1, b4); fma2(acc[1][5], a1, b5); fma2(acc[1][6], a1, b6); fma2(acc[1][7], a1, b7); \
    fma2(acc[2][0], a2, b0); fma2(acc[2][1], a2, b1); fma2(acc[2][2], a2, b2); fma2(acc[2][3], a2, b3); \
    fma2(acc[2][4], a2, b4); fma2(acc[2][5], a2, b5); fma2(acc[2][6], a2, b6); fma2(acc[2][7], a2, b7); \
    fma2(acc[3][0], a3, b0); fma2(acc[3][1], a3, b1); fma2(acc[3][2], a3, b2); fma2(acc[3][3], a3, b3); \
    fma2(acc[3][4], a3, b4); fma2(acc[3][5], a3, b5); fma2(acc[3][6], a3, b6); fma2(acc[3][7], a3, b7);

// ================= k_main1: layer-1 GEMM, A'' built in smem; extra blocks zero Zp =================
__global__ __launch_bounds__(128) void k_main1(
    const float* __restrict__ x, const int* __restrict__ eidx,
    const float* __restrict__ eattr,
    const float* __restrict__ We, const float* __restrict__ be,
    const float* __restrict__ root, float* __restrict__ Z1)
{
    __shared__ float sA[54 * 64];
    __shared__ float sB[54 * 128];

    gdc_wait();
    gdc_launch();
    const int t = threadIdx.x;

    if (blockIdx.x >= 16) {            // blocks 16..23: zero the grouped accumulators
        const int zb = blockIdx.x - 16;
        float4* z2 = (float4*)g_Z2p;
        const int n2 = G2 * 64 * O2 / 4;
        for (int i = zb * 128 + t; i < n2; i += 8 * 128) z2[i] = make_float4(0,0,0,0);
        float4* z3 = (float4*)g_Z3p;
        const int n3 = G3 * 64 * O3 / 4;
        for (int i = zb * 128 + t; i < n3; i += 8 * 128) z3[i] = make_float4(0,0,0,0);
        return;
    }
    const int c0 = blockIdx.x * 128;

    // stage B' (54 rows x 128 cols) via cp.async
    for (int i = t; i < 54 * 32; i += 128) {
        int r = i >> 5, c4 = (i & 31) * 4;
        int c = c0 + c4;
        float4* bd = (float4*)&sB[r * 128 + c4];
        if (c < O1) {
            const float* P;
            if      (r < 36) P = We   + (size_t)r * O1;
            else if (r < 45) P = be   + (size_t)(r - 36) * O1;
            else             P = root + (size_t)(r - 45) * O1;
            cpa16(bd, P + c);
        } else *bd = make_float4(0,0,0,0);
    }
    cpa_commit();

    // build A''1 (54 x 64) in smem: edge scatter + identity
    for (int i = t; i < 54 * 64; i += 128) sA[i] = 0.f;
    __syncthreads();
    if (t < NEDGES) {
        int s = eidx[t], d = eidx[NEDGES + t];
        float xs[9];
        #pragma unroll
        for (int i = 0; i < 9; i++) xs[i] = x[s * 9 + i];
        #pragma unroll
        for (int j = 0; j < 4; j++) {
            float w = eattr[t * 4 + j];
            #pragma unroll
            for (int i = 0; i < 9; i++)
                atomicAdd(&sA[(j * 9 + i) * 64 + d], w * xs[i]);
        }
        #pragma unroll
        for (int i = 0; i < 9; i++)
            atomicAdd(&sA[(36 + i) * 64 + d], xs[i]);
    }
    if (t < 64) {
        #pragma unroll
        for (int i = 0; i < 9; i++)
            sA[(45 + i) * 64 + t] = x[t * 9 + i];
    }
    cpa_wait<0>();
    __syncthreads();

    const int tx = t & 15, ty = t >> 4;
    ull acc[4][8];
    #pragma unroll
    for (int r = 0; r < 4; r++)
        #pragma unroll
        for (int j = 0; j < 8; j++) acc[r][j] = 0ull;

    for (int r = 0; r < 54; r++) {
        const float* as = &sA[r * 64 + 8 * ty];
        ull a0 = *(const ull*)(as);
        ull a1 = *(const ull*)(as + 2);
        ull a2 = *(const ull*)(as + 4);
        ull a3 = *(const ull*)(as + 6);
        float4 bL = *(const float4*)&sB[r * 128 + 4 * tx];
        float4 bH = *(const float4*)&sB[r * 128 + 64 + 4 * tx];
        FMA_BLOCK
    }

    const int cL = c0 + 4 * tx;
    const int cH = c0 + 64 + 4 * tx;
    #pragma unroll
    for (int rp = 0; rp < 4; rp++) {
        int m = 8 * ty + 2 * rp;
        float2 v[8];
        #pragma unroll
        for (int j = 0; j < 8; j++) v[j] = unpk(acc[rp][j]);
        if (cL < O1) {
            *(float4*)&Z1[(size_t)m       * O1 + cL] = make_float4(v[0].x, v[1].x, v[2].x, v[3].x);
            *(float4*)&Z1[(size_t)(m + 1) * O1 + cL] = make_float4(v[0].y, v[1].y, v[2].y, v[3].y);
        }
        if (cH < O1) {
            *(float4*)&Z1[(size_t)m       * O1 + cH] = make_float4(v[4].x, v[5].x, v[6].x, v[7].x);
            *(float4*)&Z1[(size_t)(m + 1) * O1 + cH] = make_float4(v[4].y, v[5].y, v[6].y, v[7].y);
        }
    }
}

// ================= k_mgemm: AoutT rows = [P_j^T relu(sum Zp + b) | relu(...)^T] =================
// grid (kTiles, 6). j<5: GEMM M_j[m][k]; j==5: identity transpose. P_j built in-block.
__global__ __launch_bounds__(128) void k_mgemm(
    const float* __restrict__ Z, const float* __restrict__ bias,
    int Klen, int G, const int* __restrict__ eidx,
    const float* __restrict__ eattr, float* __restrict__ AoutT)
{
    __shared__ float sP[64 * 64];        // 16 KB
    __shared__ float sh[64 * 128];       // 32 KB

    gdc_wait();
    gdc_launch();

    const int t  = threadIdx.x;
    const int k0 = blockIdx.x * 128;
    const int j  = blockIdx.y;

    if (j == 5) {   // identity block: AoutT[5K + k][n] = relu'd h, no smem needed
        for (int i = t; i < 64 * 128; i += 128) {
            int k = i >> 6, n = i & 63;
            int kk = k0 + k;
            if (kk < Klen) {
                float v = bias[kk];
                for (int g = 0; g < G; g++)
                    v += Z[(size_t)g * 64 * Klen + (size_t)n * Klen + kk];
                AoutT[(size_t)(5 * Klen + kk) * 64 + n] = fmaxf(v, 0.f);
            }
        }
        return;
    }

    // zero P, fill relu'd h tile
    for (int i = t; i < 4096; i += 128) sP[i] = 0.f;
    for (int i = t; i < 8192; i += 128) {
        int n = i >> 7, k = i & 127;
        int kk = k0 + k;
        float v = 0.f;
        if (kk < Klen) {
            v = bias[kk];
            #pragma unroll 4
            for (int g = 0; g < G; g++)
                v += Z[(size_t)g * 64 * Klen + (size_t)n * Klen + kk];
            v = fmaxf(v, 0.f);
        }
        sh[n * 128 + k] = v;
    }
    __syncthreads();
    if (t < NEDGES) {
        int s = eidx[t], d = eidx[NEDGES + t];
        float w = (j < 4) ? eattr[t * 4 + j] : 1.f;
        atomicAdd(&sP[s * 64 + d], w);
    }
    __syncthreads();

    const int tx = t & 15, ty = t >> 4;
    ull acc[4][8];
    #pragma unroll
    for (int r = 0; r < 4; r++)
        #pragma unroll
        for (int jj = 0; jj < 8; jj++) acc[r][jj] = 0ull;

    for (int n = 0; n < 64; n++) {
        const float* as = &sP[n * 64 + 8 * ty];
        ull a0 = *(const ull*)(as);
        ull a1 = *(const ull*)(as + 2);
        ull a2 = *(const ull*)(as + 4);
        ull a3 = *(const ull*)(as + 6);
        float4 bL = *(const float4*)&sh[n * 128 + 4 * tx];
        float4 bH = *(const float4*)&sh[n * 128 + 64 + 4 * tx];
        FMA_BLOCK
    }

    // epilogue: AoutT[(j*Klen + k)*64 + m], m = 8ty..8ty+7 per k
    #pragma unroll
    for (int jc = 0; jc < 8; jc++) {
        int k = (jc < 4) ? (k0 + 4 * tx + jc) : (k0 + 64 + 4 * tx + jc - 4);
        if (k < Klen) {
            size_t row = (size_t)(j * Klen + k) * 64;
            float2 p0 = unpk(acc[0][jc]), p1 = unpk(acc[1][jc]);
            float2 p2 = unpk(acc[2][jc]), p3 = unpk(acc[3][jc]);
            *(float4*)&AoutT[row + 8 * ty]     = make_float4(p0.x, p0.y, p1.x, p1.y);
            *(float4*)&AoutT[row + 8 * ty + 4] = make_float4(p2.x, p2.y, p3.x, p3.y);
        }
    }
}

// ================= k_main: split-K GEMM, grouped atomic epilogue (group = by>>4) =================
__global__ __launch_bounds__(128) void k_main(
    const float* __restrict__ AT, int Kj, int O,
    const float* __restrict__ We, const float* __restrict__ be,
    const float* __restrict__ root, float* __restrict__ Zp, int kChunk)
{
    __shared__ float As[3][16][68];
    __shared__ float Bs[3][16][128];

    gdc_wait();
    gdc_launch();

    const int t    = threadIdx.x;
    const int Ktot = 6 * Kj;
    const int c0   = blockIdx.x * 128;
    const int k0   = blockIdx.y * kChunk;
    const int kend = min(k0 + kChunk, Ktot);
    const int nsteps = (kend - k0 + 15) >> 4;
    float* Z = Zp + (size_t)(blockIdx.y >> 4) * 64 * O;

    const int kkB   = t >> 3;
    const int cbase = (t & 7) * 16;
    const float4 z4 = make_float4(0.f, 0.f, 0.f, 0.f);

    auto stage = [&](int s, int buf) {
        const int kt = k0 + s * 16;
        const int kb = kend - kt;
        #pragma unroll
        for (int i = 0; i < 4; i++) {
            int cl = cbase + 4 * i;
            int c  = c0 + cl;
            float4* bd = (float4*)&Bs[buf][kkB][cl];
            if (kkB < kb && c < O) {
                int rr = kt + kkB;
                const float* P;
                if      (rr < 4 * Kj) P = We   + (size_t)rr * O;
                else if (rr < 5 * Kj) P = be   + (size_t)(rr - 4 * Kj) * O;
                else                  P = root + (size_t)(rr - 5 * Kj) * O;
                cpa16(bd, P + c);
            } else *bd = z4;
        }
        #pragma unroll
        for (int i = 0; i < 2; i++) {
            int q  = t + 128 * i;
            int kk = q >> 4, m4 = (q & 15) * 4;
            float4* ad = (float4*)&As[buf][kk][m4];
            if (kk < kb) cpa16(ad, AT + (size_t)(kt + kk) * 64 + m4);
            else         *ad = z4;
        }
        cpa_commit();
    };

    stage(0, 0);
    if (nsteps > 1) stage(1, 1);

    const int tx = t & 15, ty = t >> 4;
    ull acc[4][8];
    #pragma unroll
    for (int r = 0; r < 4; r++)
        #pragma unroll
        for (int j = 0; j < 8; j++) acc[r][j] = 0ull;

    for (int s = 0; s < nsteps; s++) {
        const int buf = s % 3;
        if (s + 2 < nsteps)      { stage(s + 2, (s + 2) % 3); cpa_wait<2>(); }
        else if (s + 1 < nsteps) { cpa_wait<1>(); }
        else                     { cpa_wait<0>(); }
        __syncthreads();

        #pragma unroll
        for (int kk = 0; kk < 16; kk++) {
            const float* as = &As[buf][kk][8 * ty];
            ull a0 = *(const ull*)(as);
            ull a1 = *(const ull*)(as + 2);
            ull a2 = *(const ull*)(as + 4);
            ull a3 = *(const ull*)(as + 6);
            float4 bL = *(const float4*)&Bs[buf][kk][4 * tx];
            float4 bH = *(const float4*)&Bs[buf][kk][64 + 4 * tx];
            FMA_BLOCK
        }
        __syncthreads();
    }

    const int cL = c0 + 4 * tx;
    const int cH = c0 + 64 + 4 * tx;
    #pragma unroll
    for (int rp = 0; rp < 4; rp++) {
        int m = 8 * ty + 2 * rp;
        float2 v[8];
        #pragma unroll
        for (int j = 0; j < 8; j++) v[j] = unpk(acc[rp][j]);
        if (cL < O) {
            #pragma unroll
            for (int j = 0; j < 4; j++) {
                atomicAdd(&Z[(size_t)m       * O + cL + j], v[j].x);
                atomicAdd(&Z[(size_t)(m + 1) * O + cL + j], v[j].y);
            }
        }
        if (cH < O) {
            #pragma unroll
            for (int j = 0; j < 4; j++) {
                atomicAdd(&Z[(size_t)m       * O + cH + j], v[4 + j].x);
                atomicAdd(&Z[(size_t)(m + 1) * O + cH + j], v[4 + j].y);
            }
        }
    }
}

// ================= fused FCN head (sums Z3p groups, relu inline) =================
__global__ __launch_bounds__(256) void k_head(
    const float* __restrict__ Z3p, const int* __restrict__ batch,
    const float* __restrict__ b3,
    const float* __restrict__ W1, const float* __restrict__ c1,
    const float* __restrict__ W2, const float* __restrict__ c2,
    const float* __restrict__ W3, const float* __restrict__ c3,
    const float* __restrict__ W4, const float* __restrict__ c4,
    float* __restrict__ out)
{
    __shared__ float gS[100];
    __shared__ float s1[1000];
    __shared__ float part[200];
    __shared__ float s2[100];
    __shared__ float s3[50];
    __shared__ int   sb[NNODES];

    gdc_wait();

    const int g = blockIdx.x;
    const int t = threadIdx.x;

    if (t < NNODES) sb[t] = batch[t];
    __syncthreads();

    if (t < 100) {
        float bo = b3[t];
        float a = 0.f;
        for (int n = 0; n < NNODES; n++) {
            if (sb[n] == g) {
                float v = bo;
                #pragma unroll
                for (int gg = 0; gg < G3; gg++)
                    v += Z3p[gg * 64 * O3 + n * O3 + t];
                a += fmaxf(v, 0.f);
            }
        }
        gS[t] = a;
    }
    __syncthreads();

    for (int f = t; f < 1000; f += 256) {
        float a = c1[f];
        for (int kq = 0; kq < 100; kq++) a += gS[kq] * W1[kq * 1000 + f];
        s1[f] = fmaxf(a, 0.f);
    }
    __syncthreads();

    if (t < 200) {
        int f = t % 100, hh = t / 100;
        float a = 0.f;
        int kq0 = hh * 500;
        for (int kq = kq0; kq < kq0 + 500; kq++) a += s1[kq] * W2[kq * 100 + f];
        part[t] = a;
    }
    __syncthreads();
    if (t < 100) s2[t] = fmaxf(part[t] + part[100 + t] + c2[t], 0.f);
    __syncthreads();

    if (t < 50) {
        float a = c3[t];
        for (int kq = 0; kq < 100; kq++) a += s2[kq] * W3[kq * 50 + t];
        s3[t] = fmaxf(a, 0.f);
    }
    __syncthreads();

    if (t < 32) {
        float a = (t < 50) ? s3[t] * W4[t] : 0.f;
        if (t + 32 < 50) a += s3[t + 32] * W4[t + 32];
        #pragma unroll
        for (int o = 16; o > 0; o >>= 1)
            a += __shfl_xor_sync(0xffffffffu, a, o);
        if (t == 0) out[g] = a + c4[0];
    }
}

// ---------------- launch (6 PDL-chained kernels) ----------------
extern "C" void kernel_launch(void* const* d_in, const int* in_sizes, int n_in,
                              void* d_out, int out_size)
{
    const float* x     = (const float*)d_in[0];
    const int*   eidx  = (const int*)  d_in[1];
    const float* eattr = (const float*)d_in[2];
    const int*   batch = (const int*)  d_in[3];
    const float *We1 = (const float*)d_in[4],  *be1 = (const float*)d_in[5];
    const float *ro1 = (const float*)d_in[6],  *b1  = (const float*)d_in[7];
    const float *We2 = (const float*)d_in[8],  *be2 = (const float*)d_in[9];
    const float *ro2 = (const float*)d_in[10], *b2  = (const float*)d_in[11];
    const float *We3 = (const float*)d_in[12], *be3 = (const float*)d_in[13];
    const float *ro3 = (const float*)d_in[14], *b3  = (const float*)d_in[15];
    const float *W1  = (const float*)d_in[16], *c1  = (const float*)d_in[17];
    const float *W2  = (const float*)d_in[18], *c2  = (const float*)d_in[19];
    const float *W3  = (const float*)d_in[20], *c3  = (const float*)d_in[21];
    const float *W4  = (const float*)d_in[22], *c4  = (const float*)d_in[23];

    float *A2T, *A3T, *Z1, *Z2p, *Z3p;
    cudaGetSymbolAddress((void**)&A2T, g_A2T);
    cudaGetSymbolAddress((void**)&A3T, g_A3T);
    cudaGetSymbolAddress((void**)&Z1,  g_Z1);
    cudaGetSymbolAddress((void**)&Z2p, g_Z2p);
    cudaGetSymbolAddress((void**)&Z3p, g_Z3p);

    cudaLaunchAttribute attr;
    attr.id = cudaLaunchAttributeProgrammaticStreamSerialization;
    attr.val.programmaticStreamSerializationAllowed = 1;

    auto mkcfg = [&](int gx, int gy, int nt) {
        cudaLaunchConfig_t cf{};
        cf.gridDim  = dim3((unsigned)gx, (unsigned)gy, 1);
        cf.blockDim = dim3((unsigned)nt, 1, 1);
        cf.dynamicSmemBytes = 0;
        cf.stream = 0;
        cf.attrs = &attr;
        cf.numAttrs = 1;
        return cf;
    };

    cudaLaunchConfig_t cf;

    // 1) layer-1 GEMM (A'' in smem) + zero grouped accumulators
    cf = mkcfg(24, 1, 128);
    cudaLaunchKernelEx(&cf, k_main1, x, eidx, eattr, We1, be1, ro1, Z1);

    // 2) build A''2 from relu(Z1 + b1): 16 k-tiles x 6 j
    cf = mkcfg(16, 6, 128);
    cudaLaunchKernelEx(&cf, k_mgemm, (const float*)Z1, b1, K2, 1, eidx, eattr, A2T);

    // 3) layer-2 GEMM: 4 col tiles x 125 K-slices, grouped atomics (<=16-way)
    cf = mkcfg(4, 125, 128);
    cudaLaunchKernelEx(&cf, k_main, (const float*)A2T, K2, O2, We2, be2, ro2, Z2p, 96);

    // 4) build A''3 from relu(sum Z2p + b2): 4 k-tiles x 6 j
    cf = mkcfg(4, 6, 128);
    cudaLaunchKernelEx(&cf, k_mgemm, (const float*)Z2p, b2, K3, G2, eidx, eattr, A3T);

    // 5) layer-3 GEMM: 1 col tile x 94 K-slices, grouped atomics
    cf = mkcfg(1, 94, 128);
    cudaLaunchKernelEx(&cf, k_main, (const float*)A3T, K3, O3, We3, be3, ro3, Z3p, 32);

    // 6) head (sums Z3p groups, relu inline)
    cf = mkcfg(NGRAPH, 1, 256);
    cudaLaunchKernelEx(&cf, k_head, (const float*)Z3p, batch, b3,
                       W1, c1, W2, c2, W3, c3, W4, c4, (float*)d_out);
}

// round 13
// speedup vs baseline: 1.4956x; 1.4956x over previous
#include <cuda_runtime.h>
#include <cstdint>

#define NNODES 64
#define NEDGES 128
#define NGRAPH 4

typedef unsigned long long ull;

#define O1 2000
#define O2 500
#define O3 100
#define K2 2000
#define K3 500
#define G2 16
#define G3 12
#define SHS 132   // sh row stride (floats); 132*4=528 bytes, 16B aligned

// ---------------- scratch ----------------
__device__ float g_A2T[6 * K2 * 64];
__device__ float g_A3T[6 * K3 * 64];
__device__ float g_Z1 [64 * O1];
__device__ float g_Z2p[G2 * 64 * O2];
__device__ float g_Z3p[G3 * 64 * O3];

// ---------------- helpers ----------------
__device__ __forceinline__ void gdc_wait() {
    asm volatile("griddepcontrol.wait;" ::: "memory");
}
__device__ __forceinline__ void gdc_launch() {
    asm volatile("griddepcontrol.launch_dependents;" ::: "memory");
}
__device__ __forceinline__ ull dup2(float x) {
    ull r; asm("mov.b64 %0, {%1, %1};" : "=l"(r) : "f"(x)); return r;
}
__device__ __forceinline__ void fma2(ull &d, ull a, ull b) {
    asm("fma.rn.f32x2 %0, %1, %2, %3;" : "=l"(d) : "l"(a), "l"(b), "l"(d));
}
__device__ __forceinline__ float2 unpk(ull v) {
    float2 r; asm("mov.b64 {%0, %1}, %2;" : "=f"(r.x), "=f"(r.y) : "l"(v)); return r;
}
__device__ __forceinline__ void cpa16(void* dst, const void* src) {
    uint32_t d = (uint32_t)__cvta_generic_to_shared(dst);
    asm volatile("cp.async.cg.shared.global [%0], [%1], 16;\n" :: "r"(d), "l"(src));
}
__device__ __forceinline__ void cpa_commit() {
    asm volatile("cp.async.commit_group;\n" ::: "memory");
}
template<int N> __device__ __forceinline__ void cpa_wait() {
    asm volatile("cp.async.wait_group %0;\n" :: "n"(N) : "memory");
}

#define FMA_BLOCK \
    ull b0 = dup2(bL.x), b1 = dup2(bL.y), b2 = dup2(bL.z), b3 = dup2(bL.w); \
    ull b4 = dup2(bH.x), b5 = dup2(bH.y), b6 = dup2(bH.z), b7 = dup2(bH.w); \
    fma2(acc[0][0], a0, b0); fma2(acc[0][1], a0, b1); fma2(acc[0][2], a0, b2); fma2(acc[0][3], a0, b3); \
    fma2(acc[0][4], a0, b4); fma2(acc[0][5], a0, b5); fma2(acc[0][6], a0, b6); fma2(acc[0][7], a0, b7); \
    fma2(acc[1][0], a1, b0); fma2(acc[1][1], a1, b1); fma2(acc[1][2], a1, b2); fma2(acc[1][3], a1, b3); \
    fma2(acc[1][4], a1, b4); fma2(acc[1][5], a1, b5); fma2(acc[1][6], a1, b6); fma2(acc[1][7], a1, b7); \
    fma2(acc[2][0], a2, b0); fma2(acc[2][1], a2, b1); fma2(acc[2][2], a2, b2); fma2(acc[2][3], a2, b3); \
    fma2(acc[2][4], a2, b4); fma2(acc[2][5], a2, b5); fma2(acc[2][6], a2, b6); fma2(acc[2][7], a2, b7); \
    fma2(acc[3][0], a3, b0); fma2(acc[3][1], a3, b1); fma2(acc[3][2], a3, b2); fma2(acc[3][3], a3, b3); \
    fma2(acc[3][4], a3, b4); fma2(acc[3][5], a3, b5); fma2(acc[3][6], a3, b6); fma2(acc[3][7], a3, b7);

// ================= k_main1: layer-1 GEMM (A'' in smem); extra blocks zero Zp =================
__global__ __launch_bounds__(128) void k_main1(
    const float* __restrict__ x, const int* __restrict__ eidx,
    const float* __restrict__ eattr,
    const float* __restrict__ We, const float* __restrict__ be,
    const float* __restrict__ root, float* __restrict__ Z1)
{
    __shared__ float sA[54 * 64];
    __shared__ float sB[54 * 128];

    gdc_wait();
    gdc_launch();
    const int t = threadIdx.x;

    if (blockIdx.x >= 16) {            // blocks 16..47: zero grouped accumulators
        const int zb = blockIdx.x - 16;
        float4* z2 = (float4*)g_Z2p;
        const int n2 = G2 * 64 * O2 / 4;
        for (int i = zb * 128 + t; i < n2; i += 32 * 128) z2[i] = make_float4(0,0,0,0);
        float4* z3 = (float4*)g_Z3p;
        const int n3 = G3 * 64 * O3 / 4;
        for (int i = zb * 128 + t; i < n3; i += 32 * 128) z3[i] = make_float4(0,0,0,0);
        return;
    }
    const int c0 = blockIdx.x * 128;

    for (int i = t; i < 54 * 32; i += 128) {
        int r = i >> 5, c4 = (i & 31) * 4;
        int c = c0 + c4;
        float4* bd = (float4*)&sB[r * 128 + c4];
        if (c < O1) {
            const float* P;
            if      (r < 36) P = We   + (size_t)r * O1;
            else if (r < 45) P = be   + (size_t)(r - 36) * O1;
            else             P = root + (size_t)(r - 45) * O1;
            cpa16(bd, P + c);
        } else *bd = make_float4(0,0,0,0);
    }
    cpa_commit();

    for (int i = t; i < 54 * 64; i += 128) sA[i] = 0.f;
    __syncthreads();
    if (t < NEDGES) {
        int s = eidx[t], d = eidx[NEDGES + t];
        float xs[9];
        #pragma unroll
        for (int i = 0; i < 9; i++) xs[i] = x[s * 9 + i];
        #pragma unroll
        for (int j = 0; j < 4; j++) {
            float w = eattr[t * 4 + j];
            #pragma unroll
            for (int i = 0; i < 9; i++)
                atomicAdd(&sA[(j * 9 + i) * 64 + d], w * xs[i]);
        }
        #pragma unroll
        for (int i = 0; i < 9; i++)
            atomicAdd(&sA[(36 + i) * 64 + d], xs[i]);
    }
    if (t < 64) {
        #pragma unroll
        for (int i = 0; i < 9; i++)
            sA[(45 + i) * 64 + t] = x[t * 9 + i];
    }
    cpa_wait<0>();
    __syncthreads();

    const int tx = t & 15, ty = t >> 4;
    ull acc[4][8];
    #pragma unroll
    for (int r = 0; r < 4; r++)
        #pragma unroll
        for (int j = 0; j < 8; j++) acc[r][j] = 0ull;

    for (int r = 0; r < 54; r++) {
        const float* as = &sA[r * 64 + 8 * ty];
        ull a0 = *(const ull*)(as);
        ull a1 = *(const ull*)(as + 2);
        ull a2 = *(const ull*)(as + 4);
        ull a3 = *(const ull*)(as + 6);
        float4 bL = *(const float4*)&sB[r * 128 + 4 * tx];
        float4 bH = *(const float4*)&sB[r * 128 + 64 + 4 * tx];
        FMA_BLOCK
    }

    const int cL = c0 + 4 * tx;
    const int cH = c0 + 64 + 4 * tx;
    #pragma unroll
    for (int rp = 0; rp < 4; rp++) {
        int m = 8 * ty + 2 * rp;
        float2 v[8];
        #pragma unroll
        for (int j = 0; j < 8; j++) v[j] = unpk(acc[rp][j]);
        if (cL < O1) {
            *(float4*)&Z1[(size_t)m       * O1 + cL] = make_float4(v[0].x, v[1].x, v[2].x, v[3].x);
            *(float4*)&Z1[(size_t)(m + 1) * O1 + cL] = make_float4(v[0].y, v[1].y, v[2].y, v[3].y);
        }
        if (cH < O1) {
            *(float4*)&Z1[(size_t)m       * O1 + cH] = make_float4(v[4].x, v[5].x, v[6].x, v[7].x);
            *(float4*)&Z1[(size_t)(m + 1) * O1 + cH] = make_float4(v[4].y, v[5].y, v[6].y, v[7].y);
        }
    }
}

// ================= k_mgemm<G>: AoutT rows = [P_j^T relu(sum Zp + b) | relu^T] =================
// grid (kTiles, 6). High-MLP group sum; j==5 via smem transpose.
template<int G>
__global__ __launch_bounds__(128) void k_mgemm(
    const float* __restrict__ Z, const float* __restrict__ bias, int Klen,
    const int* __restrict__ eidx, const float* __restrict__ eattr,
    float* __restrict__ AoutT)
{
    __shared__ float sP[64 * 64];
    __shared__ float sh[64 * SHS];

    gdc_wait();
    gdc_launch();

    const int t  = threadIdx.x;
    const int k0 = blockIdx.x * 128;
    const int j  = blockIdx.y;

    // fill relu'd h tile into sh[n][k] — coalesced, G independent loads per element
    for (int i = t; i < 64 * 32; i += 128) {
        int n = i >> 5, k4 = (i & 31) << 2;
        int kk = k0 + k4;
        float4 v = make_float4(0.f, 0.f, 0.f, 0.f);
        if (kk < Klen) {
            float4 p[G];
            #pragma unroll
            for (int g = 0; g < G; g++)
                p[g] = *(const float4*)&Z[(size_t)g * 64 * Klen + (size_t)n * Klen + kk];
            v = *(const float4*)&bias[kk];
            #pragma unroll
            for (int g = 0; g < G; g++) {
                v.x += p[g].x; v.y += p[g].y; v.z += p[g].z; v.w += p[g].w;
            }
            v.x = fmaxf(v.x, 0.f); v.y = fmaxf(v.y, 0.f);
            v.z = fmaxf(v.z, 0.f); v.w = fmaxf(v.w, 0.f);
        }
        *(float4*)&sh[n * SHS + k4] = v;
    }

    if (j == 5) {   // identity block: transpose through smem
        __syncthreads();
        int k = k0 + t;
        if (k < Klen) {
            float* dst = AoutT + (size_t)(5 * Klen + k) * 64;
            #pragma unroll
            for (int n4 = 0; n4 < 64; n4 += 4) {
                float4 vv = make_float4(sh[(n4 + 0) * SHS + t],
                                        sh[(n4 + 1) * SHS + t],
                                        sh[(n4 + 2) * SHS + t],
                                        sh[(n4 + 3) * SHS + t]);
                *(float4*)&dst[n4] = vv;
            }
        }
        return;
    }

    // build P_j in smem
    for (int i = t; i < 4096; i += 128) sP[i] = 0.f;
    __syncthreads();
    if (t < NEDGES) {
        int s = eidx[t], d = eidx[NEDGES + t];
        float w = (j < 4) ? eattr[t * 4 + j] : 1.f;
        atomicAdd(&sP[s * 64 + d], w);
    }
    __syncthreads();

    const int tx = t & 15, ty = t >> 4;
    ull acc[4][8];
    #pragma unroll
    for (int r = 0; r < 4; r++)
        #pragma unroll
        for (int jj = 0; jj < 8; jj++) acc[r][jj] = 0ull;

    for (int n = 0; n < 64; n++) {
        const float* as = &sP[n * 64 + 8 * ty];
        ull a0 = *(const ull*)(as);
        ull a1 = *(const ull*)(as + 2);
        ull a2 = *(const ull*)(as + 4);
        ull a3 = *(const ull*)(as + 6);
        float4 bL = *(const float4*)&sh[n * SHS + 4 * tx];
        float4 bH = *(const float4*)&sh[n * SHS + 64 + 4 * tx];
        FMA_BLOCK
    }

    #pragma unroll
    for (int jc = 0; jc < 8; jc++) {
        int k = (jc < 4) ? (k0 + 4 * tx + jc) : (k0 + 64 + 4 * tx + jc - 4);
        if (k < Klen) {
            size_t row = (size_t)(j * Klen + k) * 64;
            float2 p0 = unpk(acc[0][jc]), p1 = unpk(acc[1][jc]);
            float2 p2 = unpk(acc[2][jc]), p3 = unpk(acc[3][jc]);
            *(float4*)&AoutT[row + 8 * ty]     = make_float4(p0.x, p0.y, p1.x, p1.y);
            *(float4*)&AoutT[row + 8 * ty + 4] = make_float4(p2.x, p2.y, p3.x, p3.y);
        }
    }
}

// ================= k_main: split-K GEMM, grouped atomics (group = by>>3) =================
__global__ __launch_bounds__(128) void k_main(
    const float* __restrict__ AT, int Kj, int O,
    const float* __restrict__ We, const float* __restrict__ be,
    const float* __restrict__ root, float* __restrict__ Zp, int kChunk)
{
    __shared__ float As[3][16][68];
    __shared__ float Bs[3][16][128];

    gdc_wait();
    gdc_launch();

    const int t    = threadIdx.x;
    const int Ktot = 6 * Kj;
    const int c0   = blockIdx.x * 128;
    const int k0   = blockIdx.y * kChunk;
    const int kend = min(k0 + kChunk, Ktot);
    const int nsteps = (kend - k0 + 15) >> 4;
    float* Z = Zp + (size_t)(blockIdx.y >> 3) * 64 * O;

    const int kkB   = t >> 3;
    const int cbase = (t & 7) * 16;
    const float4 z4 = make_float4(0.f, 0.f, 0.f, 0.f);

    auto stage = [&](int s, int buf) {
        const int kt = k0 + s * 16;
        const int kb = kend - kt;
        #pragma unroll
        for (int i = 0; i < 4; i++) {
            int cl = cbase + 4 * i;
            int c  = c0 + cl;
            float4* bd = (float4*)&Bs[buf][kkB][cl];
            if (kkB < kb && c < O) {
                int rr = kt + kkB;
                const float* P;
                if      (rr < 4 * Kj) P = We   + (size_t)rr * O;
                else if (rr < 5 * Kj) P = be   + (size_t)(rr - 4 * Kj) * O;
                else                  P = root + (size_t)(rr - 5 * Kj) * O;
                cpa16(bd, P + c);
            } else *bd = z4;
        }
        #pragma unroll
        for (int i = 0; i < 2; i++) {
            int q  = t + 128 * i;
            int kk = q >> 4, m4 = (q & 15) * 4;
            float4* ad = (float4*)&As[buf][kk][m4];
            if (kk < kb) cpa16(ad, AT + (size_t)(kt + kk) * 64 + m4);
            else         *ad = z4;
        }
        cpa_commit();
    };

    stage(0, 0);
    if (nsteps > 1) stage(1, 1);

    const int tx = t & 15, ty = t >> 4;
    ull acc[4][8];
    #pragma unroll
    for (int r = 0; r < 4; r++)
        #pragma unroll
        for (int j = 0; j < 8; j++) acc[r][j] = 0ull;

    for (int s = 0; s < nsteps; s++) {
        const int buf = s % 3;
        if (s + 2 < nsteps)      { stage(s + 2, (s + 2) % 3); cpa_wait<2>(); }
        else if (s + 1 < nsteps) { cpa_wait<1>(); }
        else                     { cpa_wait<0>(); }
        __syncthreads();

        #pragma unroll
        for (int kk = 0; kk < 16; kk++) {
            const float* as = &As[buf][kk][8 * ty];
            ull a0 = *(const ull*)(as);
            ull a1 = *(const ull*)(as + 2);
            ull a2 = *(const ull*)(as + 4);
            ull a3 = *(const ull*)(as + 6);
            float4 bL = *(const float4*)&Bs[buf][kk][4 * tx];
            float4 bH = *(const float4*)&Bs[buf][kk][64 + 4 * tx];
            FMA_BLOCK
        }
        __syncthreads();
    }

    const int cL = c0 + 4 * tx;
    const int cH = c0 + 64 + 4 * tx;
    #pragma unroll
    for (int rp = 0; rp < 4; rp++) {
        int m = 8 * ty + 2 * rp;
        float2 v[8];
        #pragma unroll
        for (int j = 0; j < 8; j++) v[j] = unpk(acc[rp][j]);
        if (cL < O) {
            #pragma unroll
            for (int j = 0; j < 4; j++) {
                atomicAdd(&Z[(size_t)m       * O + cL + j], v[j].x);
                atomicAdd(&Z[(size_t)(m + 1) * O + cL + j], v[j].y);
            }
        }
        if (cH < O) {
            #pragma unroll
            for (int j = 0; j < 4; j++) {
                atomicAdd(&Z[(size_t)m       * O + cH + j], v[4 + j].x);
                atomicAdd(&Z[(size_t)(m + 1) * O + cH + j], v[4 + j].y);
            }
        }
    }
}

// ================= fused FCN head (sums Z3p groups, relu inline) =================
__global__ __launch_bounds__(256) void k_head(
    const float* __restrict__ Z3p, const int* __restrict__ batch,
    const float* __restrict__ b3,
    const float* __restrict__ W1, const float* __restrict__ c1,
    const float* __restrict__ W2, const float* __restrict__ c2,
    const float* __restrict__ W3, const float* __restrict__ c3,
    const float* __restrict__ W4, const float* __restrict__ c4,
    float* __restrict__ out)
{
    __shared__ float gS[100];
    __shared__ float s1[1000];
    __shared__ float part[200];
    __shared__ float s2[100];
    __shared__ float s3[50];
    __shared__ int   sb[NNODES];

    gdc_wait();

    const int g = blockIdx.x;
    const int t = threadIdx.x;

    if (t < NNODES) sb[t] = batch[t];
    __syncthreads();

    if (t < 100) {
        float bo = b3[t];
        float a = 0.f;
        for (int n = 0; n < NNODES; n++) {
            if (sb[n] == g) {
                float p[G3];
                #pragma unroll
                for (int gg = 0; gg < G3; gg++)
                    p[gg] = Z3p[gg * 64 * O3 + n * O3 + t];
                float v = bo;
                #pragma unroll
                for (int gg = 0; gg < G3; gg++) v += p[gg];
                a += fmaxf(v, 0.f);
            }
        }
        gS[t] = a;
    }
    __syncthreads();

    for (int f = t; f < 1000; f += 256) {
        float a = c1[f];
        for (int kq = 0; kq < 100; kq++) a += gS[kq] * W1[kq * 1000 + f];
        s1[f] = fmaxf(a, 0.f);
    }
    __syncthreads();

    if (t < 200) {
        int f = t % 100, hh = t / 100;
        float a = 0.f;
        int kq0 = hh * 500;
        for (int kq = kq0; kq < kq0 + 500; kq++) a += s1[kq] * W2[kq * 100 + f];
        part[t] = a;
    }
    __syncthreads();
    if (t < 100) s2[t] = fmaxf(part[t] + part[100 + t] + c2[t], 0.f);
    __syncthreads();

    if (t < 50) {
        float a = c3[t];
        for (int kq = 0; kq < 100; kq++) a += s2[kq] * W3[kq * 50 + t];
        s3[t] = fmaxf(a, 0.f);
    }
    __syncthreads();

    if (t < 32) {
        float a = (t < 50) ? s3[t] * W4[t] : 0.f;
        if (t + 32 < 50) a += s3[t + 32] * W4[t + 32];
        #pragma unroll
        for (int o = 16; o > 0; o >>= 1)
            a += __shfl_xor_sync(0xffffffffu, a, o);
        if (t == 0) out[g] = a + c4[0];
    }
}

// ---------------- launch (6 PDL-chained kernels) ----------------
extern "C" void kernel_launch(void* const* d_in, const int* in_sizes, int n_in,
                              void* d_out, int out_size)
{
    const float* x     = (const float*)d_in[0];
    const int*   eidx  = (const int*)  d_in[1];
    const float* eattr = (const float*)d_in[2];
    const int*   batch = (const int*)  d_in[3];
    const float *We1 = (const float*)d_in[4],  *be1 = (const float*)d_in[5];
    const float *ro1 = (const float*)d_in[6],  *b1  = (const float*)d_in[7];
    const float *We2 = (const float*)d_in[8],  *be2 = (const float*)d_in[9];
    const float *ro2 = (const float*)d_in[10], *b2  = (const float*)d_in[11];
    const float *We3 = (const float*)d_in[12], *be3 = (const float*)d_in[13];
    const float *ro3 = (const float*)d_in[14], *b3  = (const float*)d_in[15];
    const float *W1  = (const float*)d_in[16], *c1  = (const float*)d_in[17];
    const float *W2  = (const float*)d_in[18], *c2  = (const float*)d_in[19];
    const float *W3  = (const float*)d_in[20], *c3  = (const float*)d_in[21];
    const float *W4  = (const float*)d_in[22], *c4  = (const float*)d_in[23];

    float *A2T, *A3T, *Z1, *Z2p, *Z3p;
    cudaGetSymbolAddress((void**)&A2T, g_A2T);
    cudaGetSymbolAddress((void**)&A3T, g_A3T);
    cudaGetSymbolAddress((void**)&Z1,  g_Z1);
    cudaGetSymbolAddress((void**)&Z2p, g_Z2p);
    cudaGetSymbolAddress((void**)&Z3p, g_Z3p);

    cudaLaunchAttribute attr;
    attr.id = cudaLaunchAttributeProgrammaticStreamSerialization;
    attr.val.programmaticStreamSerializationAllowed = 1;

    auto mkcfg = [&](int gx, int gy, int nt) {
        cudaLaunchConfig_t cf{};
        cf.gridDim  = dim3((unsigned)gx, (unsigned)gy, 1);
        cf.blockDim = dim3((unsigned)nt, 1, 1);
        cf.dynamicSmemBytes = 0;
        cf.stream = 0;
        cf.attrs = &attr;
        cf.numAttrs = 1;
        return cf;
    };

    cudaLaunchConfig_t cf;

    // 1) layer-1 GEMM (16 tiles) + zero accumulators (32 blocks)
    cf = mkcfg(48, 1, 128);
    cudaLaunchKernelEx(&cf, k_main1, x, eidx, eattr, We1, be1, ro1, Z1);

    // 2) build A''2 from relu(Z1 + b1): 16 k-tiles x 6 j
    cf = mkcfg(16, 6, 128);
    cudaLaunchKernelEx(&cf, k_mgemm<1>, (const float*)Z1, b1, K2, eidx, eattr, A2T);

    // 3) layer-2 GEMM: 4 col tiles x 125 slices, 16 groups (<=8-way contention)
    cf = mkcfg(4, 125, 128);
    cudaLaunchKernelEx(&cf, k_main, (const float*)A2T, K2, O2, We2, be2, ro2, Z2p, 96);

    // 4) build A''3 from relu(sum Z2p + b2): 4 k-tiles x 6 j
    cf = mkcfg(4, 6, 128);
    cudaLaunchKernelEx(&cf, k_mgemm<G2>, (const float*)Z2p, b2, K3, eidx, eattr, A3T);

    // 5) layer-3 GEMM: 1 col tile x 94 slices, 12 groups
    cf = mkcfg(1, 94, 128);
    cudaLaunchKernelEx(&cf, k_main, (const float*)A3T, K3, O3, We3, be3, ro3, Z3p, 32);

    // 6) head
    cf = mkcfg(NGRAPH, 1, 256);
    cudaLaunchKernelEx(&cf, k_head, (const float*)Z3p, batch, b3,
                       W1, c1, W2, c2, W3, c3, W4, c4, (float*)d_out);
}